// round 1
// baseline (speedup 1.0000x reference)
#include <cuda_runtime.h>

#define B_SZ 2048
#define H_SZ 512
#define D_SZ 32

// Scratch (device globals — no allocation allowed)
__device__ float g_H1[B_SZ * H_SZ];      // tanh layer-1 activations
__device__ float g_H2[B_SZ * H_SZ];      // tanh layer-2 activations
__device__ float g_Et[H_SZ * H_SZ];      // Et[k][m] = W2[m,k] * sum_j W1[j,m]*W3[k,j]
__device__ float g_divpart[8 * B_SZ];    // per-N-tile divergence partials

// ---------------------------------------------------------------------------
// K0: Et[k][m] = W2[m,k] * M[m,k],  M[m,k] = sum_{j<32} W1[j,m] * W3[k,j]
// ---------------------------------------------------------------------------
__global__ void k0_precompute(const float* __restrict__ W1,
                              const float* __restrict__ W2,
                              const float* __restrict__ W3) {
    int g = blockIdx.x * blockDim.x + threadIdx.x;   // 512*512 threads
    int k = g & (H_SZ - 1);
    int m = g >> 9;
    float s = 0.f;
#pragma unroll
    for (int j = 0; j < D_SZ; j++)
        s = fmaf(W1[j * H_SZ + m], W3[k * D_SZ + j], s);
    g_Et[k * H_SZ + m] = W2[m * H_SZ + k] * s;
}

// ---------------------------------------------------------------------------
// K1: H1[b][m] = tanh(b1[m] + sum_{j<32} x[b,j]*W1[j,m] + t*W1[32,m])
// ---------------------------------------------------------------------------
__global__ void k1_h1(const float* __restrict__ t,
                      const float* __restrict__ x,
                      const float* __restrict__ W1,
                      const float* __restrict__ b1) {
    __shared__ float sx[33];
    int b = blockIdx.x;
    int m = threadIdx.x;                 // 512 threads
    if (m < 33) sx[m] = (m == 32) ? t[0] : x[b * 33 + m];
    __syncthreads();
    float acc = b1[m];
#pragma unroll
    for (int j = 0; j < 33; j++)
        acc = fmaf(sx[j], W1[j * H_SZ + m], acc);
    g_H1[b * H_SZ + m] = tanhf(acc);
}

// ---------------------------------------------------------------------------
// Tiled GEMM (M=2048, N=512, K=512), BM=BN=64, BK=16, 256 threads, 4x4/thread.
// MODE 0: H2 = tanh(H1 @ W2 + b2)      (A=g_H1, B=W2 param)
// MODE 1: div partials: rowsum over N-tile of (1-H1^2) .* ((1-H2^2) @ Et)
//         (A = 1-g_H2^2, B = g_Et, nothing stored except g_divpart)
// ---------------------------------------------------------------------------
template <int MODE>
__global__ void gemm_k(const float* __restrict__ Bglob,
                       const float* __restrict__ bias) {
    const int bm = blockIdx.x * 64;
    const int bn = blockIdx.y * 64;

    __shared__ float As[16][68];   // padded (68 floats => 16B-aligned rows)
    __shared__ float Bs[16][64];
    __shared__ float red[64][16];

    const float* Ap = (MODE == 0) ? g_H1 : g_H2;
    const float* Bp = (MODE == 0) ? Bglob : g_Et;

    const int tid   = threadIdx.x;
    const int tx    = tid & 15;
    const int ty    = tid >> 4;
    const int a_row = tid >> 2;
    const int a_col = (tid & 3) << 2;
    const int b_row = tid >> 4;
    const int b_col = (tid & 15) << 2;

    float acc[4][4] = {};

    for (int k0 = 0; k0 < 512; k0 += 16) {
        float4 av = *(const float4*)(Ap + (bm + a_row) * 512 + k0 + a_col);
        if (MODE == 1) {
            av.x = 1.f - av.x * av.x; av.y = 1.f - av.y * av.y;
            av.z = 1.f - av.z * av.z; av.w = 1.f - av.w * av.w;
        }
        float4 bv = *(const float4*)(Bp + (k0 + b_row) * 512 + bn + b_col);
        __syncthreads();   // previous iter's smem reads done
        As[a_col + 0][a_row] = av.x;
        As[a_col + 1][a_row] = av.y;
        As[a_col + 2][a_row] = av.z;
        As[a_col + 3][a_row] = av.w;
        *(float4*)&Bs[b_row][b_col] = bv;
        __syncthreads();
#pragma unroll
        for (int k = 0; k < 16; k++) {
            float4 a = *(const float4*)&As[k][ty * 4];
            float4 b = *(const float4*)&Bs[k][tx * 4];
            acc[0][0] = fmaf(a.x, b.x, acc[0][0]);
            acc[0][1] = fmaf(a.x, b.y, acc[0][1]);
            acc[0][2] = fmaf(a.x, b.z, acc[0][2]);
            acc[0][3] = fmaf(a.x, b.w, acc[0][3]);
            acc[1][0] = fmaf(a.y, b.x, acc[1][0]);
            acc[1][1] = fmaf(a.y, b.y, acc[1][1]);
            acc[1][2] = fmaf(a.y, b.z, acc[1][2]);
            acc[1][3] = fmaf(a.y, b.w, acc[1][3]);
            acc[2][0] = fmaf(a.z, b.x, acc[2][0]);
            acc[2][1] = fmaf(a.z, b.y, acc[2][1]);
            acc[2][2] = fmaf(a.z, b.z, acc[2][2]);
            acc[2][3] = fmaf(a.z, b.w, acc[2][3]);
            acc[3][0] = fmaf(a.w, b.x, acc[3][0]);
            acc[3][1] = fmaf(a.w, b.y, acc[3][1]);
            acc[3][2] = fmaf(a.w, b.z, acc[3][2]);
            acc[3][3] = fmaf(a.w, b.w, acc[3][3]);
        }
    }

    if (MODE == 0) {
#pragma unroll
        for (int i = 0; i < 4; i++) {
            int row = bm + ty * 4 + i;
            int col = bn + tx * 4;
            float4 o;
            o.x = tanhf(acc[i][0] + bias[col + 0]);
            o.y = tanhf(acc[i][1] + bias[col + 1]);
            o.z = tanhf(acc[i][2] + bias[col + 2]);
            o.w = tanhf(acc[i][3] + bias[col + 3]);
            *(float4*)&g_H2[row * 512 + col] = o;
        }
    } else {
#pragma unroll
        for (int i = 0; i < 4; i++) {
            int row = bm + ty * 4 + i;
            int col = bn + tx * 4;
            float4 h1 = *(const float4*)&g_H1[row * 512 + col];
            float s = 0.f;
            s = fmaf(1.f - h1.x * h1.x, acc[i][0], s);
            s = fmaf(1.f - h1.y * h1.y, acc[i][1], s);
            s = fmaf(1.f - h1.z * h1.z, acc[i][2], s);
            s = fmaf(1.f - h1.w * h1.w, acc[i][3], s);
            red[ty * 4 + i][tx] = s;
        }
        __syncthreads();
        if (tid < 64) {
            float s = 0.f;
#pragma unroll
            for (int p = 0; p < 16; p++) s += red[tid][p];
            g_divpart[blockIdx.y * B_SZ + bm + tid] = s;
        }
    }
}

// ---------------------------------------------------------------------------
// K4: dx[b][d] = b3[d] + sum_k H2[b,k]*W3[k,d]; div[b] = sum of 8 partials.
// 256 threads handle 8 batch rows x 32 cols.
// ---------------------------------------------------------------------------
__global__ void k4_out(const float* __restrict__ W3,
                       const float* __restrict__ b3,
                       float* __restrict__ out) {
    __shared__ float sh[8 * 512];
    const int b0  = blockIdx.x * 8;
    const int tid = threadIdx.x;            // 256
    for (int idx = tid; idx < 8 * 512; idx += 256)
        sh[idx] = g_H2[b0 * 512 + idx];
    __syncthreads();
    const int r = tid >> 5;
    const int d = tid & 31;
    const int b = b0 + r;
    float acc = b3[d];
#pragma unroll 16
    for (int k = 0; k < 512; k++)
        acc = fmaf(sh[r * 512 + k], W3[k * D_SZ + d], acc);
    out[b * 33 + d] = acc;
    if (d == 0) {
        float s = 0.f;
#pragma unroll
        for (int p = 0; p < 8; p++) s += g_divpart[p * B_SZ + b];
        out[b * 33 + 32] = s;
    }
}

// ---------------------------------------------------------------------------
extern "C" void kernel_launch(void* const* d_in, const int* in_sizes, int n_in,
                              void* d_out, int out_size) {
    const float* t  = (const float*)d_in[0];
    const float* x  = (const float*)d_in[1];
    const float* W1 = (const float*)d_in[2];
    const float* b1 = (const float*)d_in[3];
    const float* W2 = (const float*)d_in[4];
    const float* b2 = (const float*)d_in[5];
    const float* W3 = (const float*)d_in[6];
    const float* b3 = (const float*)d_in[7];
    float* out = (float*)d_out;

    k0_precompute<<<(H_SZ * H_SZ) / 256, 256>>>(W1, W2, W3);
    k1_h1<<<B_SZ, H_SZ>>>(t, x, W1, b1);
    dim3 g(B_SZ / 64, H_SZ / 64);
    gemm_k<0><<<g, 256>>>(W2, b2);           // H2 = tanh(H1@W2 + b2)
    gemm_k<1><<<g, 256>>>(nullptr, nullptr); // divergence partials
    k4_out<<<B_SZ / 8, 256>>>(W3, b3, out);  // dx + div finalize
}

// round 4
// speedup vs baseline: 1.8484x; 1.8484x over previous
#include <cuda_runtime.h>
#include <cuda_bf16.h>
#include <cstdint>

#define B_SZ 2048
#define H_SZ 512
#define D_SZ 32

// ---------------- scratch (device globals; no allocation allowed) ----------
__device__ __align__(16) __nv_bfloat16 g_H1h[B_SZ * H_SZ];
__device__ __align__(16) __nv_bfloat16 g_H1l[B_SZ * H_SZ];
__device__ __align__(16) float         g_D1 [B_SZ * H_SZ];   // 1 - h1^2
__device__ __align__(16) float         g_H2 [B_SZ * H_SZ];
__device__ __align__(16) __nv_bfloat16 g_D2h[B_SZ * H_SZ];   // 1 - h2^2 split
__device__ __align__(16) __nv_bfloat16 g_D2l[B_SZ * H_SZ];
__device__ __align__(16) __nv_bfloat16 g_Bt0h[H_SZ * H_SZ];  // W2^T split
__device__ __align__(16) __nv_bfloat16 g_Bt0l[H_SZ * H_SZ];
__device__ __align__(16) __nv_bfloat16 g_Bdvh[H_SZ * H_SZ];  // E[n][k] split
__device__ __align__(16) __nv_bfloat16 g_Bdvl[H_SZ * H_SZ];
__device__ float g_divpart[8 * B_SZ];

// ---------------- helpers ---------------------------------------------------
__device__ __forceinline__ void bf16split(float x, __nv_bfloat16& h, __nv_bfloat16& l) {
    h = __float2bfloat16_rn(x);
    l = __float2bfloat16_rn(x - __bfloat162float(h));
}
__device__ __forceinline__ uint32_t smem_u32(const void* p) {
    return (uint32_t)__cvta_generic_to_shared(p);
}

#define LDSM4(d, addr)                                                          \
    asm volatile("ldmatrix.sync.aligned.m8n8.x4.shared.b16 {%0,%1,%2,%3}, [%4];"\
        : "=r"((d)[0]), "=r"((d)[1]), "=r"((d)[2]), "=r"((d)[3]) : "r"(addr))

#define MMA_BF16(c, a, b0v, b1v)                                                \
    asm volatile("mma.sync.aligned.m16n8k16.row.col.f32.bf16.bf16.f32 "         \
        "{%0,%1,%2,%3},{%4,%5,%6,%7},{%8,%9},{%0,%1,%2,%3};"                    \
        : "+f"((c)[0]), "+f"((c)[1]), "+f"((c)[2]), "+f"((c)[3])                 \
        : "r"((a)[0]), "r"((a)[1]), "r"((a)[2]), "r"((a)[3]), "r"(b0v), "r"(b1v))

// ---------------------------------------------------------------------------
// K0: g_Bt0*[n][k] = split(W2[k][n]);
//     g_Bdv*[n][k] = split(W2[n][k] * sum_j W1[j][n]*W3[k][j])
// ---------------------------------------------------------------------------
__global__ void k0_pre(const float* __restrict__ W1,
                       const float* __restrict__ W2,
                       const float* __restrict__ W3) {
    __shared__ float tW2[32][33];
    __shared__ float sW3[32][33];
    const int tx = threadIdx.x, ty = threadIdx.y;
    const int k0 = blockIdx.x * 32, n0 = blockIdx.y * 32;

    tW2[ty][tx] = W2[(k0 + ty) * H_SZ + n0 + tx];
    sW3[ty][tx] = W3[(k0 + ty) * D_SZ + tx];
    __syncthreads();

    const int n = n0 + ty;
    const int k = k0 + tx;
    bf16split(tW2[tx][ty], g_Bt0h[n * H_SZ + k], g_Bt0l[n * H_SZ + k]);

    float s = 0.f;
#pragma unroll
    for (int j = 0; j < D_SZ; j++)
        s = fmaf(W1[j * H_SZ + n], sW3[tx][j], s);
    bf16split(W2[n * H_SZ + k] * s, g_Bdvh[n * H_SZ + k], g_Bdvl[n * H_SZ + k]);
}

// ---------------------------------------------------------------------------
// K1: H1 = tanh([x,t] @ W1 + b1) -> bf16 split; D1 = 1 - H1^2 (fp32)
// ---------------------------------------------------------------------------
__global__ void __launch_bounds__(512) k1_h1(const float* __restrict__ t,
                                             const float* __restrict__ x,
                                             const float* __restrict__ W1,
                                             const float* __restrict__ b1) {
    __shared__ float sx[16][33];
    const int b0 = blockIdx.x * 16;
    const int m  = threadIdx.x;
    for (int idx = m; idx < 16 * 33; idx += 512) {
        int r = idx / 33, j = idx % 33;
        sx[r][j] = (j == 32) ? t[0] : x[(b0 + r) * 33 + j];
    }
    float w[33];
#pragma unroll
    for (int j = 0; j < 33; j++) w[j] = W1[j * H_SZ + m];
    float bb = b1[m];
    __syncthreads();
#pragma unroll 4
    for (int r = 0; r < 16; r++) {
        float acc = bb;
#pragma unroll
        for (int j = 0; j < 33; j++) acc = fmaf(sx[r][j], w[j], acc);
        float h = tanhf(acc);
        const int o = (b0 + r) * H_SZ + m;
        bf16split(h, g_H1h[o], g_H1l[o]);
        g_D1[o] = 1.f - h * h;
    }
}

// ---------------------------------------------------------------------------
// bf16-split mma.sync GEMM.  CTA tile 128(M) x 64(N), K=512 in chunks of 32.
// grid (16, 8), 256 threads, 8 warps (4 m x 2 n), warp tile 32x32.
// MODE 0: C = H1 @ W2   -> H2 = tanh(C + b2), D2 = 1-H2^2 (split)
// MODE 1: C = D2 @ E^T  -> divpart[ny][row] = sum_col D1[row,col]*C[row,col]
// ---------------------------------------------------------------------------
// smem: padded rows of 40 bf16 (80 B) for conflict-free ldmatrix
#define SA_H 0
#define SA_L 10240
#define SB_H 20480
#define SB_L 25600
#define SMEM_BYTES 30720

template <int MODE>
__global__ void __launch_bounds__(256) gemm_mma(const float* __restrict__ bias) {
    __shared__ __align__(16) unsigned char smem[SMEM_BYTES];
    const int tid  = threadIdx.x;
    const int lane = tid & 31;
    const int wid  = tid >> 5;
    const int wm   = wid & 3;
    const int wn   = wid >> 2;
    const int bm   = blockIdx.x * 128;
    const int bn   = blockIdx.y * 64;

    const __nv_bfloat16* __restrict__ Ah = (MODE == 0) ? g_H1h : g_D2h;
    const __nv_bfloat16* __restrict__ Al = (MODE == 0) ? g_H1l : g_D2l;
    const __nv_bfloat16* __restrict__ Bh = (MODE == 0) ? g_Bt0h : g_Bdvh;
    const __nv_bfloat16* __restrict__ Bl = (MODE == 0) ? g_Bt0l : g_Bdvl;

    const uint32_t sbase = smem_u32(smem);

    // copy indices: A 128 rows x 32 k (4 uint4/row), 2 per thread; B 64 rows, 1/thread
    const int arow0 = tid >> 2;              // rows 0..63  (i=0) / +64 (i=1)
    const int akq   = tid & 3;
    const int brow  = tid >> 2;              // 0..63
    const int bkq   = tid & 3;

    float cacc[2][4][4] = {};

    uint4 pa[4], pb[2];
    {   // prologue: chunk 0
        const int k0 = 0;
#pragma unroll
        for (int i = 0; i < 2; i++) {
            int row = arow0 + i * 64;
            pa[i]     = *(const uint4*)(Ah + (size_t)(bm + row) * H_SZ + k0 + akq * 8);
            pa[i + 2] = *(const uint4*)(Al + (size_t)(bm + row) * H_SZ + k0 + akq * 8);
        }
        pb[0] = *(const uint4*)(Bh + (size_t)(bn + brow) * H_SZ + k0 + bkq * 8);
        pb[1] = *(const uint4*)(Bl + (size_t)(bn + brow) * H_SZ + k0 + bkq * 8);
    }

    // per-warp ldmatrix base offsets
    const int lrow = (lane & 7) + ((lane >> 3) & 1) * 8;
    const int lcol = ((lane >> 4) & 1) * 16;

#pragma unroll 1
    for (int c = 0; c < 16; ++c) {
        __syncthreads();
        {   // store prefetched chunk to smem
#pragma unroll
            for (int i = 0; i < 2; i++) {
                int row = arow0 + i * 64;
                *(uint4*)(smem + SA_H + row * 80 + akq * 16) = pa[i];
                *(uint4*)(smem + SA_L + row * 80 + akq * 16) = pa[i + 2];
            }
            *(uint4*)(smem + SB_H + brow * 80 + bkq * 16) = pb[0];
            *(uint4*)(smem + SB_L + brow * 80 + bkq * 16) = pb[1];
        }
        __syncthreads();

        {   // prefetch next chunk (wraps harmlessly on last iter)
            const int k0 = ((c + 1) & 15) * 32;
#pragma unroll
            for (int i = 0; i < 2; i++) {
                int row = arow0 + i * 64;
                pa[i]     = *(const uint4*)(Ah + (size_t)(bm + row) * H_SZ + k0 + akq * 8);
                pa[i + 2] = *(const uint4*)(Al + (size_t)(bm + row) * H_SZ + k0 + akq * 8);
            }
            pb[0] = *(const uint4*)(Bh + (size_t)(bn + brow) * H_SZ + k0 + bkq * 8);
            pb[1] = *(const uint4*)(Bl + (size_t)(bn + brow) * H_SZ + k0 + bkq * 8);
        }

        // compute chunk (2 x k16)
#pragma unroll
        for (int kk = 0; kk < 2; kk++) {
            uint32_t afh[2][4], afl[2][4], bfh[2][4], bfl[2][4];
#pragma unroll
            for (int m = 0; m < 2; m++) {
                uint32_t ad = sbase + SA_H +
                    (uint32_t)((wm * 32 + m * 16 + lrow) * 80 + lcol + kk * 32);
                LDSM4(afh[m], ad);
                LDSM4(afl[m], ad + (SA_L - SA_H));
            }
#pragma unroll
            for (int p = 0; p < 2; p++) {
                uint32_t bd = sbase + SB_H +
                    (uint32_t)((wn * 32 + p * 16 + lrow) * 80 + lcol + kk * 32);
                LDSM4(bfh[p], bd);
                LDSM4(bfl[p], bd + (SB_L - SB_H));
            }
#pragma unroll
            for (int m = 0; m < 2; m++)
#pragma unroll
                for (int n = 0; n < 4; n++) {
                    const int p = n >> 1, o = n & 1;
                    MMA_BF16(cacc[m][n], afh[m], bfh[p][o], bfh[p][o + 2]);
                    MMA_BF16(cacc[m][n], afh[m], bfl[p][o], bfl[p][o + 2]);
                    MMA_BF16(cacc[m][n], afl[m], bfh[p][o], bfh[p][o + 2]);
                }
        }
    }

    __syncthreads();

    if (MODE == 0) {
#pragma unroll
        for (int m = 0; m < 2; m++)
#pragma unroll
            for (int h = 0; h < 2; h++) {
                const int row = bm + wm * 32 + m * 16 + (lane >> 2) + h * 8;
#pragma unroll
                for (int n = 0; n < 4; n++) {
                    const int col = bn + wn * 32 + n * 8 + ((lane & 3) << 1);
                    float v0 = tanhf(cacc[m][n][h * 2 + 0] + __ldg(&bias[col + 0]));
                    float v1 = tanhf(cacc[m][n][h * 2 + 1] + __ldg(&bias[col + 1]));
                    *(float2*)&g_H2[(size_t)row * H_SZ + col] = make_float2(v0, v1);
                    float d0 = 1.f - v0 * v0, d1v = 1.f - v1 * v1;
                    __nv_bfloat16 h0, l0, h1b, l1;
                    bf16split(d0, h0, l0);
                    bf16split(d1v, h1b, l1);
                    *(__nv_bfloat162*)&g_D2h[(size_t)row * H_SZ + col] =
                        __nv_bfloat162(h0, h1b);
                    *(__nv_bfloat162*)&g_D2l[(size_t)row * H_SZ + col] =
                        __nv_bfloat162(l0, l1);
                }
            }
    } else {
        float sr[4] = {0.f, 0.f, 0.f, 0.f};
#pragma unroll
        for (int m = 0; m < 2; m++)
#pragma unroll
            for (int h = 0; h < 2; h++) {
                const int row = bm + wm * 32 + m * 16 + (lane >> 2) + h * 8;
#pragma unroll
                for (int n = 0; n < 4; n++) {
                    const int col = bn + wn * 32 + n * 8 + ((lane & 3) << 1);
                    float2 w = *(const float2*)&g_D1[(size_t)row * H_SZ + col];
                    sr[m * 2 + h] += w.x * cacc[m][n][h * 2 + 0]
                                   + w.y * cacc[m][n][h * 2 + 1];
                }
            }
#pragma unroll
        for (int i = 0; i < 4; i++) {
            sr[i] += __shfl_xor_sync(0xffffffffu, sr[i], 1);
            sr[i] += __shfl_xor_sync(0xffffffffu, sr[i], 2);
        }
        float* red = (float*)smem;   // 128 x 2 floats (reuse tile smem)
        if ((lane & 3) == 0) {
#pragma unroll
            for (int m = 0; m < 2; m++)
#pragma unroll
                for (int h = 0; h < 2; h++) {
                    const int rl = wm * 32 + m * 16 + (lane >> 2) + h * 8;
                    red[rl * 2 + wn] = sr[m * 2 + h];
                }
        }
        __syncthreads();
        if (tid < 128)
            g_divpart[blockIdx.y * B_SZ + bm + tid] = red[tid * 2] + red[tid * 2 + 1];
    }
}

// ---------------------------------------------------------------------------
// K4: dx[b][d] = b3[d] + sum_k H2[b,k]*W3[k,d]; div[b] = sum of 8 partials.
// ---------------------------------------------------------------------------
__global__ void __launch_bounds__(256) k4_out(const float* __restrict__ W3,
                                              const float* __restrict__ b3,
                                              float* __restrict__ out) {
    __shared__ float sh[8 * 512];
    const int b0  = blockIdx.x * 8;
    const int tid = threadIdx.x;
    for (int idx = tid; idx < 8 * 512; idx += 256)
        sh[idx] = g_H2[b0 * 512 + idx];
    __syncthreads();
    const int r = tid >> 5;
    const int d = tid & 31;
    const int b = b0 + r;
    float acc = b3[d];
#pragma unroll 16
    for (int k = 0; k < 512; k++)
        acc = fmaf(sh[r * 512 + k], W3[k * D_SZ + d], acc);
    out[b * 33 + d] = acc;
    if (d == 0) {
        float s = 0.f;
#pragma unroll
        for (int p = 0; p < 8; p++) s += g_divpart[p * B_SZ + b];
        out[b * 33 + 32] = s;
    }
}

// ---------------------------------------------------------------------------
extern "C" void kernel_launch(void* const* d_in, const int* in_sizes, int n_in,
                              void* d_out, int out_size) {
    const float* t  = (const float*)d_in[0];
    const float* x  = (const float*)d_in[1];
    const float* W1 = (const float*)d_in[2];
    const float* b1 = (const float*)d_in[3];
    const float* W2 = (const float*)d_in[4];
    const float* b2 = (const float*)d_in[5];
    const float* W3 = (const float*)d_in[6];
    const float* b3 = (const float*)d_in[7];
    float* out = (float*)d_out;

    k0_pre<<<dim3(16, 16), dim3(32, 32)>>>(W1, W2, W3);
    k1_h1<<<128, 512>>>(t, x, W1, b1);
    dim3 g(16, 8);
    gemm_mma<0><<<g, 256>>>(b2);        // H2 = tanh(H1 @ W2 + b2), D2 split
    gemm_mma<1><<<g, 256>>>(nullptr);   // divergence partials
    k4_out<<<B_SZ / 8, 256>>>(W3, b3, out);
}

// round 7
// speedup vs baseline: 2.1385x; 1.1570x over previous
#include <cuda_runtime.h>
#include <cuda_bf16.h>
#include <cstdint>

#define B_SZ 2048
#define H_SZ 512
#define D_SZ 32

// ---------------- scratch (device globals; no allocation allowed) ----------
__device__ __align__(16) __nv_bfloat16 g_H1h[B_SZ * H_SZ];
__device__ __align__(16) __nv_bfloat16 g_H1l[B_SZ * H_SZ];
__device__ __align__(16) float         g_D1 [B_SZ * H_SZ];   // 1 - h1^2
__device__ __align__(16) float         g_H2 [B_SZ * H_SZ];
__device__ __align__(16) __nv_bfloat16 g_D2h[B_SZ * H_SZ];   // 1 - h2^2 split
__device__ __align__(16) __nv_bfloat16 g_D2l[B_SZ * H_SZ];
__device__ __align__(16) __nv_bfloat16 g_Bt0h[H_SZ * H_SZ];  // W2^T split
__device__ __align__(16) __nv_bfloat16 g_Bt0l[H_SZ * H_SZ];
__device__ __align__(16) __nv_bfloat16 g_Bdvh[H_SZ * H_SZ];  // E[n][k] split
__device__ __align__(16) __nv_bfloat16 g_Bdvl[H_SZ * H_SZ];
__device__ float g_divpart[8 * B_SZ];

// ---------------- helpers ---------------------------------------------------
__device__ __forceinline__ void bf16split(float x, __nv_bfloat16& h, __nv_bfloat16& l) {
    h = __float2bfloat16_rn(x);
    l = __float2bfloat16_rn(x - __bfloat162float(h));
}
__device__ __forceinline__ uint32_t smem_u32(const void* p) {
    return (uint32_t)__cvta_generic_to_shared(p);
}
__device__ __forceinline__ void cp16(uint32_t dst, const void* src) {
    asm volatile("cp.async.cg.shared.global [%0], [%1], 16;" :: "r"(dst), "l"(src));
}
#define CP_COMMIT() asm volatile("cp.async.commit_group;" ::: "memory")
#define CP_WAIT(n)  asm volatile("cp.async.wait_group %0;" :: "n"(n) : "memory")

#define LDSM4(d, addr)                                                          \
    asm volatile("ldmatrix.sync.aligned.m8n8.x4.shared.b16 {%0,%1,%2,%3}, [%4];"\
        : "=r"((d)[0]), "=r"((d)[1]), "=r"((d)[2]), "=r"((d)[3]) : "r"(addr))

#define MMA_BF16(c, a, b0v, b1v)                                                \
    asm volatile("mma.sync.aligned.m16n8k16.row.col.f32.bf16.bf16.f32 "         \
        "{%0,%1,%2,%3},{%4,%5,%6,%7},{%8,%9},{%0,%1,%2,%3};"                    \
        : "+f"((c)[0]), "+f"((c)[1]), "+f"((c)[2]), "+f"((c)[3])                 \
        : "r"((a)[0]), "r"((a)[1]), "r"((a)[2]), "r"((a)[3]), "r"(b0v), "r"(b1v))

// ---------------------------------------------------------------------------
// K0: g_Bt0*[n][k] = split(W2[k][n]);
//     g_Bdv*[n][k] = split(W2[n][k] * sum_j W1[j][n]*W3[k][j])
// ---------------------------------------------------------------------------
__global__ void k0_pre(const float* __restrict__ W1,
                       const float* __restrict__ W2,
                       const float* __restrict__ W3) {
    __shared__ float tW2[32][33];
    __shared__ float sW3[32][33];
    const int tx = threadIdx.x, ty = threadIdx.y;
    const int k0 = blockIdx.x * 32, n0 = blockIdx.y * 32;

    tW2[ty][tx] = W2[(k0 + ty) * H_SZ + n0 + tx];
    sW3[ty][tx] = W3[(k0 + ty) * D_SZ + tx];
    __syncthreads();

    const int n = n0 + ty;
    const int k = k0 + tx;
    bf16split(tW2[tx][ty], g_Bt0h[n * H_SZ + k], g_Bt0l[n * H_SZ + k]);

    float s = 0.f;
#pragma unroll
    for (int j = 0; j < D_SZ; j++)
        s = fmaf(W1[j * H_SZ + n], sW3[tx][j], s);
    bf16split(W2[n * H_SZ + k] * s, g_Bdvh[n * H_SZ + k], g_Bdvl[n * H_SZ + k]);
}

// ---------------------------------------------------------------------------
// K1: H1 = tanh([x,t] @ W1 + b1) -> bf16 split; D1 = 1 - H1^2 (fp32)
// ---------------------------------------------------------------------------
__global__ void __launch_bounds__(512) k1_h1(const float* __restrict__ t,
                                             const float* __restrict__ x,
                                             const float* __restrict__ W1,
                                             const float* __restrict__ b1) {
    __shared__ float sx[16][33];
    const int b0 = blockIdx.x * 16;
    const int m  = threadIdx.x;
    for (int idx = m; idx < 16 * 33; idx += 512) {
        int r = idx / 33, j = idx % 33;
        sx[r][j] = (j == 32) ? t[0] : x[(b0 + r) * 33 + j];
    }
    float w[33];
#pragma unroll
    for (int j = 0; j < 33; j++) w[j] = W1[j * H_SZ + m];
    float bb = b1[m];
    __syncthreads();
#pragma unroll 4
    for (int r = 0; r < 16; r++) {
        float acc = bb;
#pragma unroll
        for (int j = 0; j < 33; j++) acc = fmaf(sx[r][j], w[j], acc);
        float h = tanhf(acc);
        const int o = (b0 + r) * H_SZ + m;
        bf16split(h, g_H1h[o], g_H1l[o]);
        g_D1[o] = 1.f - h * h;
    }
}

// ---------------------------------------------------------------------------
// bf16-split mma.sync GEMM, cp.async 4-stage pipeline.
// CTA tile 128(M) x 64(N), K=512 in 16 chunks of 32. grid (16,8), 256 thr.
// MODE 0: C = H1 @ W2   -> H2 = tanh(C + b2), D2 = 1-H2^2 (split)
// MODE 1: C = D2 @ E^T  -> divpart[ny][row] = sum_col D1[row,col]*C[row,col]
// ---------------------------------------------------------------------------
// per-stage smem layout (80B-padded rows, conflict-free ldmatrix):
#define SA_H 0
#define SA_L 10240
#define SB_H 20480
#define SB_L 25600
#define STG  30720
#define NSTAGE 4
#define GEMM_SMEM (STG * NSTAGE)   // 122880

template <int MODE>
__global__ void __launch_bounds__(256) gemm_mma(const float* __restrict__ bias) {
    extern __shared__ __align__(16) unsigned char smem[];
    const int tid  = threadIdx.x;
    const int lane = tid & 31;
    const int wid  = tid >> 5;
    const int wm   = wid & 3;
    const int wn   = wid >> 2;
    const int bm   = blockIdx.x * 128;
    const int bn   = blockIdx.y * 64;

    const __nv_bfloat16* __restrict__ Ah = (MODE == 0) ? g_H1h : g_D2h;
    const __nv_bfloat16* __restrict__ Al = (MODE == 0) ? g_H1l : g_D2l;
    const __nv_bfloat16* __restrict__ Bh = (MODE == 0) ? g_Bt0h : g_Bdvh;
    const __nv_bfloat16* __restrict__ Bl = (MODE == 0) ? g_Bt0l : g_Bdvl;

    const uint32_t sb = smem_u32(smem);

    // copy assignment: 6 cp.async(16B) per thread per chunk
    const int crow = tid >> 2;                  // 0..63
    const int cg8  = (tid & 3) * 8;             // element offset of granule
    const size_t aoff1 = (size_t)(bm + crow) * H_SZ + cg8;
    const size_t aoff2 = (size_t)(bm + crow + 64) * H_SZ + cg8;
    const size_t boff  = (size_t)(bn + crow) * H_SZ + cg8;
    const uint32_t dR1 = crow * 80 + (tid & 3) * 16;
    const uint32_t dR2 = (crow + 64) * 80 + (tid & 3) * 16;

    float cacc[2][4][4] = {};

    // ldmatrix lane addressing within warp
    const int lrow = (lane & 7) + ((lane >> 3) & 1) * 8;
    const int lcol = ((lane >> 4) & 1) * 16;

#define ISSUE(c) do {                                                           \
        const int _k0 = (c) * 32;                                               \
        const uint32_t _st = sb + ((c) & (NSTAGE - 1)) * STG;                   \
        cp16(_st + SA_H + dR1, Ah + aoff1 + _k0);                               \
        cp16(_st + SA_H + dR2, Ah + aoff2 + _k0);                               \
        cp16(_st + SA_L + dR1, Al + aoff1 + _k0);                               \
        cp16(_st + SA_L + dR2, Al + aoff2 + _k0);                               \
        cp16(_st + SB_H + dR1, Bh + boff + _k0);                                \
        cp16(_st + SB_L + dR1, Bl + boff + _k0);                                \
    } while (0)

    ISSUE(0); CP_COMMIT();
    ISSUE(1); CP_COMMIT();
    ISSUE(2); CP_COMMIT();

#pragma unroll 1
    for (int c = 0; c < 16; ++c) {
        CP_WAIT(2);
        __syncthreads();                 // stage c ready; stage c-1 fully consumed
        if (c + 3 < 16) ISSUE(c + 3);    // refills buffer (c-1)&3
        CP_COMMIT();                     // (empty group on tail iters)

        const uint32_t st = sb + (c & (NSTAGE - 1)) * STG;
#pragma unroll
        for (int kk = 0; kk < 2; kk++) {
            uint32_t afh[2][4], afl[2][4], bfh[2][4], bfl[2][4];
#pragma unroll
            for (int m = 0; m < 2; m++) {
                uint32_t ad = st + SA_H +
                    (uint32_t)((wm * 32 + m * 16 + lrow) * 80 + lcol + kk * 32);
                LDSM4(afh[m], ad);
                LDSM4(afl[m], ad + (SA_L - SA_H));
            }
#pragma unroll
            for (int p = 0; p < 2; p++) {
                uint32_t bd = st + SB_H +
                    (uint32_t)((wn * 32 + p * 16 + lrow) * 80 + lcol + kk * 32);
                LDSM4(bfh[p], bd);
                LDSM4(bfl[p], bd + (SB_L - SB_H));
            }
            // pass-major ordering: every accumulator's chained MMAs are 8 apart
#pragma unroll
            for (int m = 0; m < 2; m++)
#pragma unroll
                for (int n = 0; n < 4; n++) {
                    const int p = n >> 1, o = n & 1;
                    MMA_BF16(cacc[m][n], afh[m], bfh[p][o], bfh[p][o + 2]);
                }
#pragma unroll
            for (int m = 0; m < 2; m++)
#pragma unroll
                for (int n = 0; n < 4; n++) {
                    const int p = n >> 1, o = n & 1;
                    MMA_BF16(cacc[m][n], afh[m], bfl[p][o], bfl[p][o + 2]);
                }
#pragma unroll
            for (int m = 0; m < 2; m++)
#pragma unroll
                for (int n = 0; n < 4; n++) {
                    const int p = n >> 1, o = n & 1;
                    MMA_BF16(cacc[m][n], afl[m], bfh[p][o], bfh[p][o + 2]);
                }
        }
    }
#undef ISSUE

    __syncthreads();

    if (MODE == 0) {
#pragma unroll
        for (int m = 0; m < 2; m++)
#pragma unroll
            for (int h = 0; h < 2; h++) {
                const int row = bm + wm * 32 + m * 16 + (lane >> 2) + h * 8;
#pragma unroll
                for (int n = 0; n < 4; n++) {
                    const int col = bn + wn * 32 + n * 8 + ((lane & 3) << 1);
                    float v0 = tanhf(cacc[m][n][h * 2 + 0] + __ldg(&bias[col + 0]));
                    float v1 = tanhf(cacc[m][n][h * 2 + 1] + __ldg(&bias[col + 1]));
                    *(float2*)&g_H2[(size_t)row * H_SZ + col] = make_float2(v0, v1);
                    float d0 = 1.f - v0 * v0, d1v = 1.f - v1 * v1;
                    __nv_bfloat16 h0, l0, h1b, l1;
                    bf16split(d0, h0, l0);
                    bf16split(d1v, h1b, l1);
                    *(__nv_bfloat162*)&g_D2h[(size_t)row * H_SZ + col] =
                        __nv_bfloat162(h0, h1b);
                    *(__nv_bfloat162*)&g_D2l[(size_t)row * H_SZ + col] =
                        __nv_bfloat162(l0, l1);
                }
            }
    } else {
        float sr[4] = {0.f, 0.f, 0.f, 0.f};
#pragma unroll
        for (int m = 0; m < 2; m++)
#pragma unroll
            for (int h = 0; h < 2; h++) {
                const int row = bm + wm * 32 + m * 16 + (lane >> 2) + h * 8;
#pragma unroll
                for (int n = 0; n < 4; n++) {
                    const int col = bn + wn * 32 + n * 8 + ((lane & 3) << 1);
                    float2 w = *(const float2*)&g_D1[(size_t)row * H_SZ + col];
                    sr[m * 2 + h] += w.x * cacc[m][n][h * 2 + 0]
                                   + w.y * cacc[m][n][h * 2 + 1];
                }
            }
#pragma unroll
        for (int i = 0; i < 4; i++) {
            sr[i] += __shfl_xor_sync(0xffffffffu, sr[i], 1);
            sr[i] += __shfl_xor_sync(0xffffffffu, sr[i], 2);
        }
        float* red = (float*)smem;   // reuse tile smem: 128 rows x 2
        if ((lane & 3) == 0) {
#pragma unroll
            for (int m = 0; m < 2; m++)
#pragma unroll
                for (int h = 0; h < 2; h++) {
                    const int rl = wm * 32 + m * 16 + (lane >> 2) + h * 8;
                    red[rl * 2 + wn] = sr[m * 2 + h];
                }
        }
        __syncthreads();
        if (tid < 128)
            g_divpart[blockIdx.y * B_SZ + bm + tid] = red[tid * 2] + red[tid * 2 + 1];
    }
}

// ---------------------------------------------------------------------------
// K4: dx[b][d] = b3[d] + sum_k H2[b,k]*W3[k,d]; div[b] = sum of 8 partials.
// ---------------------------------------------------------------------------
__global__ void __launch_bounds__(256) k4_out(const float* __restrict__ W3,
                                              const float* __restrict__ b3,
                                              float* __restrict__ out) {
    __shared__ float sh[8 * 512];
    const int b0  = blockIdx.x * 8;
    const int tid = threadIdx.x;
    for (int idx = tid; idx < 8 * 512; idx += 256)
        sh[idx] = g_H2[b0 * 512 + idx];
    __syncthreads();
    const int r = tid >> 5;
    const int d = tid & 31;
    const int b = b0 + r;
    float acc = b3[d];
#pragma unroll 16
    for (int k = 0; k < 512; k++)
        acc = fmaf(sh[r * 512 + k], W3[k * D_SZ + d], acc);
    out[b * 33 + d] = acc;
    if (d == 0) {
        float s = 0.f;
#pragma unroll
        for (int p = 0; p < 8; p++) s += g_divpart[p * B_SZ + b];
        out[b * 33 + 32] = s;
    }
}

// ---------------------------------------------------------------------------
extern "C" void kernel_launch(void* const* d_in, const int* in_sizes, int n_in,
                              void* d_out, int out_size) {
    const float* t  = (const float*)d_in[0];
    const float* x  = (const float*)d_in[1];
    const float* W1 = (const float*)d_in[2];
    const float* b1 = (const float*)d_in[3];
    const float* W2 = (const float*)d_in[4];
    const float* b2 = (const float*)d_in[5];
    const float* W3 = (const float*)d_in[6];
    const float* b3 = (const float*)d_in[7];
    float* out = (float*)d_out;

    cudaFuncSetAttribute(gemm_mma<0>, cudaFuncAttributeMaxDynamicSharedMemorySize, GEMM_SMEM);
    cudaFuncSetAttribute(gemm_mma<1>, cudaFuncAttributeMaxDynamicSharedMemorySize, GEMM_SMEM);

    k0_pre<<<dim3(16, 16), dim3(32, 32)>>>(W1, W2, W3);
    k1_h1<<<128, 512>>>(t, x, W1, b1);
    dim3 g(16, 8);
    gemm_mma<0><<<g, 256, GEMM_SMEM>>>(b2);        // H2 = tanh(H1 @ W2 + b2), D2 split
    gemm_mma<1><<<g, 256, GEMM_SMEM>>>(nullptr);   // divergence partials
    k4_out<<<B_SZ / 8, 256>>>(W3, b3, out);
}